// round 7
// baseline (speedup 1.0000x reference)
#include <cuda_runtime.h>
#include <cstdint>

// ---------------------------------------------------------------------------
// DFine Multiscale Deformable Attention
//   B=16, Q=300, HIDDEN=256, N_HEADS=8, d=32
//   SPATIAL = (100,100),(50,50),(25,25),(13,13)  -> S=13294
//   NUM_POINTS = 4 per level -> p_total=16, total_points = 128
// Output = concat( out[B,Q,256], aw[B,Q,8,16] )  (float32)
// ---------------------------------------------------------------------------

#define NB        16
#define NQ        300
#define NBQ       (NB * NQ)          // 4800
#define HIDDEN    256
#define NHEADS    8
#define PTOT      16
#define NOUT0     (NBQ * HIDDEN)
#define SENC      13294

typedef unsigned long long ull;

// per-(b,q): 8 heads * 16 points * 2 coords
__device__ float g_loc[NBQ * NHEADS * PTOT * 2];

__device__ __forceinline__ ull pk2(float lo, float hi) {
    ull r; asm("mov.b64 %0, {%1,%2};" : "=l"(r) : "f"(lo), "f"(hi)); return r;
}
__device__ __forceinline__ void upk2(float& lo, float& hi, ull v) {
    asm("mov.b64 {%0,%1}, %2;" : "=f"(lo), "=f"(hi) : "l"(v));
}
#define FFMA2(d, a, b) asm("fma.rn.f32x2 %0, %1, %2, %0;" : "+l"(d) : "l"(a), "l"(b))

__device__ __forceinline__ void cp_async16(void* smem_dst, const void* gsrc) {
    unsigned sd = (unsigned)__cvta_generic_to_shared(smem_dst);
    asm volatile("cp.async.ca.shared.global [%0], [%1], 16;" :: "r"(sd), "l"(gsrc));
}
__device__ __forceinline__ void cp_commit() {
    asm volatile("cp.async.commit_group;");
}
template <int N>
__device__ __forceinline__ void cp_wait() {
    asm volatile("cp.async.wait_group %0;" :: "n"(N));
}

// ---------------------------------------------------------------------------
// Kernel A: projection GEMM + softmax + sampling locations.
// GTILE=16 rows/block (300 blocks), 384 threads = one output column each
// (256 offset cols + 128 attn cols). W is streamed through shared memory via
// a 6-stage cp.async pipeline (stage = 4 combined W rows of 384 floats), so
// L2 latency on W is fully hidden without register pressure. Hidden-state
// row pairs are pre-packed as u64 for f32x2 FMAs.
// ---------------------------------------------------------------------------
#define GTILE   16
#define NGP     (GTILE / 2)
#define KSTEP   4
#define NSTAGE  6
#define NKGRP   (HIDDEN / KSTEP)     // 64

__global__ __launch_bounds__(384, 2)
void dfine_proj_kernel(const float* __restrict__ hs,        // (BQ, 256)
                       const float* __restrict__ ref,       // (BQ, 4)
                       const float* __restrict__ W_off,     // (256, 256)
                       const float* __restrict__ b_off,     // (256,)
                       const float* __restrict__ W_attn,    // (256, 128)
                       const float* __restrict__ b_attn,    // (128,)
                       float* __restrict__ out_aw)          // d_out + NOUT0
{
    __shared__ ull   shP[NGP * 256];              // 16 KB packed hs row-pairs
    __shared__ float sW[NSTAGE][KSTEP][384];      // 36 KB W stages

    const int bq0 = blockIdx.x * GTILE;
    const int tid = threadIdx.x;                  // 0..383

    // cp.async source for this thread: one 16B chunk per stage.
    // flat float4 id f=tid: row r = f/96, chunk c = f%96.
    const int r_cp = tid / 96;
    const int c_cp = tid - r_cp * 96;
    const bool cp_is_off = (c_cp < 64);
    // dst column offset within the 384-float combined row
    const int dst_col = cp_is_off ? (4 * c_cp) : (256 + 4 * (c_cp - 64));

    // prime NSTAGE-1 stages
#pragma unroll
    for (int s = 0; s < NSTAGE - 1; ++s) {
        const int k = s * KSTEP + r_cp;
        const float* src = cp_is_off ? (W_off + (size_t)k * 256 + 4 * c_cp)
                                     : (W_attn + (size_t)k * 128 + 4 * (c_cp - 64));
        cp_async16(&sW[s][r_cp][dst_col], src);
        cp_commit();
    }

    // pack hidden states while the first W stages are in flight
    const float* hsb = hs + (size_t)bq0 * HIDDEN;
    for (int i = tid; i < NGP * 256; i += 384) {
        const int gp = i >> 8, k = i & 255;
        shP[gp * 256 + k] = pk2(hsb[(2 * gp) * 256 + k], hsb[(2 * gp + 1) * 256 + k]);
    }

    const bool is_off = (tid < 256);
    const float bias = is_off ? b_off[tid] : b_attn[tid - 256];

    ull acc2[NGP];
#pragma unroll
    for (int gp = 0; gp < NGP; ++gp) acc2[gp] = pk2(bias, bias);

#pragma unroll 1
    for (int g = 0; g < NKGRP; ++g) {
        const int slot = g % NSTAGE;

        cp_wait<NSTAGE - 2>();
        __syncthreads();

        float w0 = sW[slot][0][tid];
        float w1 = sW[slot][1][tid];
        float w2 = sW[slot][2][tid];
        float w3 = sW[slot][3][tid];
        const ull wd0 = pk2(w0, w0), wd1 = pk2(w1, w1);
        const ull wd2 = pk2(w2, w2), wd3 = pk2(w3, w3);

        const int k0 = g * KSTEP;
#pragma unroll
        for (int gp = 0; gp < NGP; ++gp) {
            const ull* row = shP + gp * 256 + k0;
            const ulonglong2 p01 = *(const ulonglong2*)(row);
            const ulonglong2 p23 = *(const ulonglong2*)(row + 2);
            FFMA2(acc2[gp], p01.x, wd0);
            FFMA2(acc2[gp], p01.y, wd1);
            FFMA2(acc2[gp], p23.x, wd2);
            FFMA2(acc2[gp], p23.y, wd3);
        }

        // issue stage g+NSTAGE-1 (into the slot consumed at iter g-1)
        const int gs = g + NSTAGE - 1;
        if (gs < NKGRP) {
            const int k = gs * KSTEP + r_cp;
            const float* src = cp_is_off ? (W_off + (size_t)k * 256 + 4 * c_cp)
                                         : (W_attn + (size_t)k * 128 + 4 * (c_cp - 64));
            cp_async16(&sW[gs % NSTAGE][r_cp][dst_col], src);
        }
        cp_commit();   // commit every iter (possibly empty) to keep group numbering
    }

    float acc[GTILE];
#pragma unroll
    for (int gp = 0; gp < NGP; ++gp)
        upk2(acc[2 * gp], acc[2 * gp + 1], acc2[gp]);

    if (!is_off) {
        // softmax over the 16 points of each head (16-lane groups)
        const int idx = tid - 256;            // h*16 + p
#pragma unroll
        for (int g = 0; g < GTILE; ++g) {
            float v = acc[g];
            float m = v;
#pragma unroll
            for (int o = 8; o; o >>= 1)
                m = fmaxf(m, __shfl_xor_sync(0xffffffffu, m, o));
            float e = __expf(v - m);
            float s = e;
#pragma unroll
            for (int o = 8; o; o >>= 1)
                s += __shfl_xor_sync(0xffffffffu, s, o);
            out_aw[(size_t)(bq0 + g) * (NHEADS * PTOT) + idx] = e / s;
        }
    } else {
        // sampling locations: loc = ref_xy + acc * (1/4) * 0.5 * ref_wh
        const int c = tid & 1;
#pragma unroll
        for (int g = 0; g < GTILE; ++g) {
            const float4 r = __ldg((const float4*)ref + (bq0 + g));
            const float base = c ? r.y : r.x;
            const float wh   = c ? r.w : r.z;
            g_loc[(size_t)(bq0 + g) * 256 + tid] = fmaf(acc[g] * 0.125f, wh, base);
        }
    }
}

// ---------------------------------------------------------------------------
// Kernel B: bilinear sampling + weighted sum (R4 layout — best measured).
// One block (256 thr) per bq; warp = head; lane = tap(4) x chanquad(8);
// front-batched 8-deep LDG.128; cross-tap shuffle reduction.
// ---------------------------------------------------------------------------
__global__ __launch_bounds__(256)
void dfine_sample_kernel(const float* __restrict__ enc,     // (B, S, 256)
                         const float* __restrict__ aw,      // (BQ, 128)
                         float* __restrict__ out)           // (BQ, 256)
{
    __shared__ int2 s_tap[128 * 4];

    const int bq  = blockIdx.x;
    const int b   = bq / NQ;
    const int tid = threadIdx.x;

    if (tid < 128) {
        const int hp = tid, hh = hp >> 4, p = hp & 15, lvl = p >> 2;
        const int w  = (lvl == 0) ? 100 : (lvl == 1) ? 50 : (lvl == 2) ? 25 : 13;
        const int st = (lvl == 0) ? 0 : (lvl == 1) ? 10000 : (lvl == 2) ? 12500 : 13125;

        const float2 l2 = ((const float2*)g_loc)[(size_t)bq * 128 + hp];
        const float a   = aw[(size_t)bq * 128 + hp];

        const float x = fmaf(l2.x, (float)w, -0.5f);
        const float y = fmaf(l2.y, (float)w, -0.5f);
        const float x0f = floorf(x), y0f = floorf(y);
        const int   x0 = (int)x0f,  y0 = (int)y0f;
        const float wx1 = x - x0f, wx0 = 1.0f - wx1;
        const float wy1 = y - y0f, wy0 = 1.0f - wy1;

        const bool vx0 = (x0 >= 0)  && (x0 < w);
        const bool vx1 = (x0 >= -1) && (x0 < w - 1);
        const bool vy0 = (y0 >= 0)  && (y0 < w);
        const bool vy1 = (y0 >= -1) && (y0 < w - 1);

        const int base = st * 256 + hh * 32;
        const int r0 = base + (y0 * w + x0) * 256;
        const int r1 = r0 + w * 256;

        const bool v00 = vy0 && vx0, v01 = vy0 && vx1;
        const bool v10 = vy1 && vx0, v11 = vy1 && vx1;
        int2* tp = s_tap + hp * 4;
        tp[0] = make_int2(v00 ? r0       : 0, __float_as_int(v00 ? wy0 * wx0 * a : 0.f));
        tp[1] = make_int2(v01 ? r0 + 256 : 0, __float_as_int(v01 ? wy0 * wx1 * a : 0.f));
        tp[2] = make_int2(v10 ? r1       : 0, __float_as_int(v10 ? wy1 * wx0 * a : 0.f));
        tp[3] = make_int2(v11 ? r1 + 256 : 0, __float_as_int(v11 ? wy1 * wx1 * a : 0.f));
    }
    __syncthreads();

    const int h    = tid >> 5;
    const int lane = tid & 31;
    const int t    = lane >> 3;         // tap 0..3
    const int dq   = (lane & 7) << 2;   // channel quad start
    const float* encb = enc + (size_t)b * (SENC * 256) + dq;

    float ax = 0.f, ay = 0.f, az = 0.f, aq = 0.f;

#pragma unroll
    for (int pb = 0; pb < PTOT; pb += 8) {
        int   idx[8];
        float wt[8];
#pragma unroll
        for (int j = 0; j < 8; ++j) {
            const int2 tp = s_tap[(h * PTOT + pb + j) * 4 + t];
            idx[j] = tp.x;
            wt[j]  = __int_as_float(tp.y);
        }
        float4 v[8];
#pragma unroll
        for (int j = 0; j < 8; ++j)
            v[j] = __ldg((const float4*)(encb + idx[j]));
#pragma unroll
        for (int j = 0; j < 8; ++j) {
            ax = fmaf(wt[j], v[j].x, ax);
            ay = fmaf(wt[j], v[j].y, ay);
            az = fmaf(wt[j], v[j].z, az);
            aq = fmaf(wt[j], v[j].w, aq);
        }
    }

    // sum across the 4 tap groups (lanes xor 8, xor 16)
#pragma unroll
    for (int o = 8; o <= 16; o <<= 1) {
        ax += __shfl_xor_sync(0xffffffffu, ax, o);
        ay += __shfl_xor_sync(0xffffffffu, ay, o);
        az += __shfl_xor_sync(0xffffffffu, az, o);
        aq += __shfl_xor_sync(0xffffffffu, aq, o);
    }

    if (lane < 8) {
        float4 r;
        r.x = ax; r.y = ay; r.z = az; r.w = aq;
        *(float4*)(out + (size_t)bq * 256 + h * 32 + dq) = r;
    }
}

// ---------------------------------------------------------------------------
extern "C" void kernel_launch(void* const* d_in, const int* in_sizes, int n_in,
                              void* d_out, int out_size)
{
    const float* hs     = (const float*)d_in[0];   // (B,Q,256)
    const float* enc    = (const float*)d_in[1];   // (B,S,256)
    const float* ref    = (const float*)d_in[2];   // (B,Q,1,4)
    const float* W_off  = (const float*)d_in[3];   // (256,256)
    const float* b_off  = (const float*)d_in[4];   // (256,)
    const float* W_attn = (const float*)d_in[5];   // (256,128)
    const float* b_attn = (const float*)d_in[6];   // (128,)

    float* out    = (float*)d_out;                 // (B,Q,256)
    float* out_aw = (float*)d_out + NOUT0;         // (B,Q,8,16)

    dfine_proj_kernel<<<NBQ / GTILE, 384>>>(hs, ref, W_off, b_off, W_attn,
                                            b_attn, out_aw);
    dfine_sample_kernel<<<NBQ, 256>>>(enc, out_aw, out);
}

// round 8
// speedup vs baseline: 1.2235x; 1.2235x over previous
#include <cuda_runtime.h>
#include <cstdint>

// ---------------------------------------------------------------------------
// DFine Multiscale Deformable Attention
//   B=16, Q=300, HIDDEN=256, N_HEADS=8, d=32
//   SPATIAL = (100,100),(50,50),(25,25),(13,13)  -> S=13294
//   NUM_POINTS = 4 per level -> p_total=16, total_points = 128
// Output = concat( out[B,Q,256], aw[B,Q,8,16] )  (float32)
// ---------------------------------------------------------------------------

#define NB        16
#define NQ        300
#define NBQ       (NB * NQ)          // 4800
#define HIDDEN    256
#define NHEADS    8
#define PTOT      16
#define NOUT0     (NBQ * HIDDEN)
#define SENC      13294

typedef unsigned long long ull;

// per-(b,q): 8 heads * 16 points * 2 coords
__device__ float g_loc[NBQ * NHEADS * PTOT * 2];

__device__ __forceinline__ ull pk2(float lo, float hi) {
    ull r; asm("mov.b64 %0, {%1,%2};" : "=l"(r) : "f"(lo), "f"(hi)); return r;
}
__device__ __forceinline__ void upk2(float& lo, float& hi, ull v) {
    asm("mov.b64 {%0,%1}, %2;" : "=f"(lo), "=f"(hi) : "l"(v));
}
#define FFMA2(d, a, b) asm("fma.rn.f32x2 %0, %1, %2, %0;" : "+l"(d) : "l"(a), "l"(b))

// ---------------------------------------------------------------------------
// Kernel A: projection GEMM + softmax + sampling locations (R4 version —
// best measured). GTILE=16 rows/block, 384 threads = one output column each.
// f32x2 packed FMA, 8-deep register W prefetch, no in-loop barriers.
// ---------------------------------------------------------------------------
#define GTILE 16

__global__ __launch_bounds__(384, 2)
void dfine_proj_kernel(const float* __restrict__ hs,        // (BQ, 256)
                       const float* __restrict__ ref,       // (BQ, 4)
                       const float* __restrict__ W_off,     // (256, 256)
                       const float* __restrict__ b_off,     // (256,)
                       const float* __restrict__ W_attn,    // (256, 128)
                       const float* __restrict__ b_attn,    // (128,)
                       float* __restrict__ out_aw)          // d_out + NOUT0
{
    __shared__ ull shP[8 * 256];              // [gp][k]: pack(hs[2gp][k], hs[2gp+1][k])
    const int bq0 = blockIdx.x * GTILE;
    const int tid = threadIdx.x;              // 0..383

    const float* hsb = hs + (size_t)bq0 * HIDDEN;
    for (int i = tid; i < 8 * 256; i += 384) {
        const int gp = i >> 8, k = i & 255;
        shP[gp * 256 + k] = pk2(hsb[(2 * gp) * 256 + k], hsb[(2 * gp + 1) * 256 + k]);
    }
    __syncthreads();

    const bool is_off = (tid < 256);
    const float* Wp = is_off ? (W_off + tid) : (W_attn + (tid - 256));
    const int    ws = is_off ? 256 : 128;
    const float  bias = is_off ? b_off[tid] : b_attn[tid - 256];

    ull acc2[8];
#pragma unroll
    for (int gp = 0; gp < 8; ++gp) acc2[gp] = pk2(bias, bias);

    float w[8];
#pragma unroll
    for (int j = 0; j < 8; ++j) w[j] = __ldg(Wp + (size_t)j * ws);

#pragma unroll 1
    for (int k0 = 0; k0 < HIDDEN; k0 += 8) {
        float wn[8];
        const bool more = (k0 + 8) < HIDDEN;
#pragma unroll
        for (int j = 0; j < 8; ++j)
            wn[j] = more ? __ldg(Wp + (size_t)(k0 + 8 + j) * ws) : 0.0f;

        ull wd[8];
#pragma unroll
        for (int j = 0; j < 8; ++j) wd[j] = pk2(w[j], w[j]);

#pragma unroll
        for (int gp = 0; gp < 8; ++gp) {
            const ull* row = shP + gp * 256 + k0;
#pragma unroll
            for (int jj = 0; jj < 4; ++jj) {
                const ulonglong2 p = *(const ulonglong2*)(row + 2 * jj);
                FFMA2(acc2[gp], p.x, wd[2 * jj]);
                FFMA2(acc2[gp], p.y, wd[2 * jj + 1]);
            }
        }
#pragma unroll
        for (int j = 0; j < 8; ++j) w[j] = wn[j];
    }

    float acc[GTILE];
#pragma unroll
    for (int gp = 0; gp < 8; ++gp)
        upk2(acc[2 * gp], acc[2 * gp + 1], acc2[gp]);

    if (!is_off) {
        // softmax over the 16 points of each head (16-lane groups)
        const int idx = tid - 256;            // h*16 + p
#pragma unroll
        for (int g = 0; g < GTILE; ++g) {
            float v = acc[g];
            float m = v;
#pragma unroll
            for (int o = 8; o; o >>= 1)
                m = fmaxf(m, __shfl_xor_sync(0xffffffffu, m, o));
            float e = __expf(v - m);
            float s = e;
#pragma unroll
            for (int o = 8; o; o >>= 1)
                s += __shfl_xor_sync(0xffffffffu, s, o);
            out_aw[(size_t)(bq0 + g) * (NHEADS * PTOT) + idx] = e / s;
        }
    } else {
        // sampling locations: loc = ref_xy + acc * (1/4) * 0.5 * ref_wh
        const int c = tid & 1;
#pragma unroll
        for (int g = 0; g < GTILE; ++g) {
            const float4 r = __ldg((const float4*)ref + (bq0 + g));
            const float base = c ? r.y : r.x;
            const float wh   = c ? r.w : r.z;
            g_loc[(size_t)(bq0 + g) * 256 + tid] = fmaf(acc[g] * 0.125f, wh, base);
        }
    }
}

// ---------------------------------------------------------------------------
// Kernel B: bilinear sampling + weighted sum. QB=8 queries per block,
// double-buffered tap setup so next query's global loads + tap math overlap
// current query's gather. Grid = 600 blocks -> fully resident, single wave.
// Per query: warp = head; lane = tap(4) x chanquad(8); 2x front-batched
// 8-deep LDG.128; cross-tap shuffle reduction.
// ---------------------------------------------------------------------------
#define QB 8

__global__ __launch_bounds__(256)
void dfine_sample_kernel(const float* __restrict__ enc,     // (B, S, 256)
                         const float* __restrict__ aw,      // (BQ, 128)
                         float* __restrict__ out)           // (BQ, 256)
{
    __shared__ int2 s_tap[2][512];            // [buf][hp*4 + tap]

    const int bq0 = blockIdx.x * QB;
    const int tid = threadIdx.x;

    // this thread's two tap tasks (task = half*256 + tid)
    const int task0 = tid,        hp0 = task0 >> 2, t0 = task0 & 3;
    const int task1 = tid + 256,  hp1 = task1 >> 2, t1 = task1 & 3;

    // per-task level constants
    const int lvl0 = (hp0 & 15) >> 2, lvl1 = (hp1 & 15) >> 2;
    const int w0_  = (lvl0 == 0) ? 100 : (lvl0 == 1) ? 50 : (lvl0 == 2) ? 25 : 13;
    const int w1_  = (lvl1 == 0) ? 100 : (lvl1 == 1) ? 50 : (lvl1 == 2) ? 25 : 13;
    const int st0  = (lvl0 == 0) ? 0 : (lvl0 == 1) ? 10000 : (lvl0 == 2) ? 12500 : 13125;
    const int st1  = (lvl1 == 0) ? 0 : (lvl1 == 1) ? 10000 : (lvl1 == 2) ? 12500 : 13125;

    // compute-phase constants
    const int h    = tid >> 5;                // warp = head
    const int lane = tid & 31;
    const int t    = lane >> 3;               // tap 0..3
    const int dq   = (lane & 7) << 2;         // channel quad start

    // ---- helper lambdas -------------------------------------------------
    auto tap_make = [](int hp, int tp, int w, int st, float2 l2, float a) -> int2 {
        const float x = fmaf(l2.x, (float)w, -0.5f);
        const float y = fmaf(l2.y, (float)w, -0.5f);
        const float x0f = floorf(x), y0f = floorf(y);
        const float wx1 = x - x0f, wy1 = y - y0f;
        const int tx = tp & 1, ty = tp >> 1;
        const int xi = (int)x0f + tx;
        const int yi = (int)y0f + ty;
        const bool valid = (xi >= 0) && (xi < w) && (yi >= 0) && (yi < w);
        const float wt = (ty ? wy1 : 1.0f - wy1) * (tx ? wx1 : 1.0f - wx1) * a;
        const int off = st * 256 + (hp >> 4) * 32 + (yi * w + xi) * 256;
        return make_int2(valid ? off : 0, __float_as_int(valid ? wt : 0.0f));
    };

    // ---- prologue: load + setup for bq0 into buf 0 ----
    float2 l0 = ((const float2*)g_loc)[(size_t)bq0 * 128 + hp0];
    float2 l1 = ((const float2*)g_loc)[(size_t)bq0 * 128 + hp1];
    float  a0 = aw[(size_t)bq0 * 128 + hp0];
    float  a1 = aw[(size_t)bq0 * 128 + hp1];
    s_tap[0][task0] = tap_make(hp0, t0, w0_, st0, l0, a0);
    s_tap[0][task1] = tap_make(hp1, t1, w1_, st1, l1, a1);

#pragma unroll 1
    for (int i = 0; i < QB; ++i) {
        __syncthreads();
        const int bq  = bq0 + i;
        const int buf = i & 1;

        // issue next query's global loads first (latency overlapped below)
        float2 nl0, nl1; float na0, na1;
        if (i + 1 < QB) {
            const int nbq = bq + 1;
            nl0 = ((const float2*)g_loc)[(size_t)nbq * 128 + hp0];
            nl1 = ((const float2*)g_loc)[(size_t)nbq * 128 + hp1];
            na0 = aw[(size_t)nbq * 128 + hp0];
            na1 = aw[(size_t)nbq * 128 + hp1];
        }

        // ---- gather for current query ----
        const int b = bq / NQ;
        const float* encb = enc + (size_t)b * (SENC * 256) + dq;
        const int2* tb = &s_tap[buf][h * PTOT * 4 + t];

        float ax = 0.f, ay = 0.f, az = 0.f, aq = 0.f;
#pragma unroll
        for (int pb = 0; pb < PTOT; pb += 8) {
            int   idx[8];
            float wt[8];
#pragma unroll
            for (int j = 0; j < 8; ++j) {
                const int2 tp = tb[(pb + j) * 4];
                idx[j] = tp.x;
                wt[j]  = __int_as_float(tp.y);
            }
            float4 v[8];
#pragma unroll
            for (int j = 0; j < 8; ++j)
                v[j] = __ldg((const float4*)(encb + idx[j]));
#pragma unroll
            for (int j = 0; j < 8; ++j) {
                ax = fmaf(wt[j], v[j].x, ax);
                ay = fmaf(wt[j], v[j].y, ay);
                az = fmaf(wt[j], v[j].z, az);
                aq = fmaf(wt[j], v[j].w, aq);
            }
        }

        // cross-tap reduction (lanes xor 8, xor 16)
#pragma unroll
        for (int o = 8; o <= 16; o <<= 1) {
            ax += __shfl_xor_sync(0xffffffffu, ax, o);
            ay += __shfl_xor_sync(0xffffffffu, ay, o);
            az += __shfl_xor_sync(0xffffffffu, az, o);
            aq += __shfl_xor_sync(0xffffffffu, aq, o);
        }
        if (lane < 8) {
            float4 r;
            r.x = ax; r.y = ay; r.z = az; r.w = aq;
            *(float4*)(out + (size_t)bq * 256 + h * 32 + dq) = r;
        }

        // ---- setup next query into the other buffer ----
        if (i + 1 < QB) {
            s_tap[buf ^ 1][task0] = tap_make(hp0, t0, w0_, st0, nl0, na0);
            s_tap[buf ^ 1][task1] = tap_make(hp1, t1, w1_, st1, nl1, na1);
        }
    }
}

// ---------------------------------------------------------------------------
extern "C" void kernel_launch(void* const* d_in, const int* in_sizes, int n_in,
                              void* d_out, int out_size)
{
    const float* hs     = (const float*)d_in[0];   // (B,Q,256)
    const float* enc    = (const float*)d_in[1];   // (B,S,256)
    const float* ref    = (const float*)d_in[2];   // (B,Q,1,4)
    const float* W_off  = (const float*)d_in[3];   // (256,256)
    const float* b_off  = (const float*)d_in[4];   // (256,)
    const float* W_attn = (const float*)d_in[5];   // (256,128)
    const float* b_attn = (const float*)d_in[6];   // (128,)

    float* out    = (float*)d_out;                 // (B,Q,256)
    float* out_aw = (float*)d_out + NOUT0;         // (B,Q,8,16)

    dfine_proj_kernel<<<NBQ / GTILE, 384>>>(hs, ref, W_off, b_off, W_attn,
                                            b_attn, out_aw);
    dfine_sample_kernel<<<NBQ / QB, 256>>>(enc, out_aw, out);
}